// round 9
// baseline (speedup 1.0000x reference)
#include <cuda_runtime.h>
#include <cuda_bf16.h>
#include <cstdint>
#include <cstddef>

#define N_NODES 8192
#define DHID 128
#define QA 32512.0f
#define QB 32256.0f

// ======================= device scratch (no cudaMalloc allowed) ==============
__device__ __align__(1024) char   g_Ah[(size_t)N_NODES * N_NODES];   // 64 MB (s8 hi limb)
__device__ __align__(1024) char   g_Al[(size_t)N_NODES * N_NODES];   // 64 MB (s8 lo limb)
__device__ __align__(1024) float  g_dinv[N_NODES];
__device__ __align__(1024) float  g_Y[(size_t)N_NODES * DHID];
__device__ __align__(1024) float  g_H[(size_t)N_NODES * DHID];
__device__ __align__(1024) float  g_P[2 * (size_t)N_NODES * DHID];   // split-K partials
__device__ __align__(1024) char   g_Bh[(size_t)DHID * N_NODES];      // [c][k] K-major, s8 hi
__device__ __align__(1024) char   g_Bl[(size_t)DHID * N_NODES];      // [c][k] K-major, s8 lo
__device__ unsigned               g_colmax[DHID];                    // float bits, per column

// ======================= helpers =============================================
__device__ __forceinline__ uint32_t smem_u32(const void* p) {
    uint32_t a;
    asm("{ .reg .u64 t; cvta.to.shared.u64 t, %1; cvt.u32.u64 %0, t; }" : "=r"(a) : "l"(p));
    return a;
}
__device__ __forceinline__ void cp_async16(uint32_t dst, const void* src) {
    asm volatile("cp.async.cg.shared.global [%0], [%1], 16;" :: "r"(dst), "l"(src) : "memory");
}
__device__ __forceinline__ void cp_commit() {
    asm volatile("cp.async.commit_group;" ::: "memory");
}
template <int N>
__device__ __forceinline__ void cp_wait() {
    asm volatile("cp.async.wait_group %0;" :: "n"(N) : "memory");
}
__device__ __forceinline__ void ldmx4(uint32_t* r, uint32_t addr) {
    asm volatile("ldmatrix.sync.aligned.m8n8.x4.shared.b16 {%0,%1,%2,%3}, [%4];"
                 : "=r"(r[0]), "=r"(r[1]), "=r"(r[2]), "=r"(r[3]) : "r"(addr));
}
// s8 MMA, k32, s32 accumulate (fragment byte-layout identical to bf16 k16)
__device__ __forceinline__ void mma_s8(int* d, const uint32_t* a, const uint32_t* b) {
    asm volatile(
        "mma.sync.aligned.m16n8k32.row.col.s32.s8.s8.s32 "
        "{%0,%1,%2,%3}, {%4,%5,%6,%7}, {%8,%9}, {%0,%1,%2,%3};"
        : "+r"(d[0]), "+r"(d[1]), "+r"(d[2]), "+r"(d[3])
        : "r"(a[0]), "r"(a[1]), "r"(a[2]), "r"(a[3]), "r"(b[0]), "r"(b[1]));
}

// async tile loader: R rows x 128 bytes (8 x 16B chunks per row), XOR swizzle
__device__ __forceinline__ void load_tile_async(
    const char* __restrict__ src, int rowbase, int kk,
    uint32_t dst, int R, int tid) {
    for (int ch = tid; ch < R * 8; ch += 256) {
        const int row = ch >> 3;
        const int cb = ch & 7;
        const char* g = src + (size_t)(rowbase + row) * N_NODES + kk + cb * 16;
        const uint32_t s = dst + row * 128 + ((cb * 16) ^ ((row & 7) * 16));
        cp_async16(s, g);
    }
}

// ======================= kernel 1: rowsum + s8 limb split of adjacency =======
__global__ void __launch_bounds__(256) prep_kernel(const float* __restrict__ adj) {
    const int row = blockIdx.x;
    const int tid = threadIdx.x;
    const float4* src = reinterpret_cast<const float4*>(adj + (size_t)row * N_NODES);
    char4* dh = reinterpret_cast<char4*>(g_Ah + (size_t)row * N_NODES);
    char4* dl = reinterpret_cast<char4*>(g_Al + (size_t)row * N_NODES);
    float sum = 0.f;
    for (int i = tid; i < N_NODES / 4; i += 256) {
        float4 v = src[i];
        sum += (v.x + v.y) + (v.z + v.w);
        int q0 = __float2int_rn(v.x * QA);
        int q1 = __float2int_rn(v.y * QA);
        int q2 = __float2int_rn(v.z * QA);
        int q3 = __float2int_rn(v.w * QA);
        int h0 = (q0 + 128) >> 8, h1 = (q1 + 128) >> 8;
        int h2 = (q2 + 128) >> 8, h3 = (q3 + 128) >> 8;
        dh[i] = make_char4((char)h0, (char)h1, (char)h2, (char)h3);
        dl[i] = make_char4((char)(q0 - (h0 << 8)), (char)(q1 - (h1 << 8)),
                           (char)(q2 - (h2 << 8)), (char)(q3 - (h3 << 8)));
    }
    #pragma unroll
    for (int o = 16; o; o >>= 1) sum += __shfl_xor_sync(0xffffffffu, sum, o);
    __shared__ float red[8];
    if ((tid & 31) == 0) red[tid >> 5] = sum;
    __syncthreads();
    if (tid == 0) {
        float s = 0.f;
        #pragma unroll
        for (int i = 0; i < 8; i++) s += red[i];
        g_dinv[row] = rsqrtf(s + 1.0f);   // A = adj + I
    }
}

// ======================= colmax reset ========================================
__global__ void zero_cmax_kernel() {
    if (threadIdx.x < DHID) g_colmax[threadIdx.x] = 0u;
}

// ======================= kernel 2: Y = H @ W  (+ per-column |dinv*Y| max) ====
template <int KD, int C>
__global__ void y_kernel(const float* __restrict__ Hin, const float* __restrict__ W) {
    extern __shared__ float Ws[];
    __shared__ unsigned smax[C];
    const int tid = threadIdx.x;
    const int nthreads = 64 * (C / 32);
    for (int i = tid; i < KD * C; i += nthreads) Ws[i] = W[i];
    for (int i = tid; i < C; i += nthreads) smax[i] = 0u;
    __syncthreads();
    const int row = blockIdx.x * 64 + (tid & 63);
    const int cg = tid >> 6;
    float acc[32];
    #pragma unroll
    for (int j = 0; j < 32; j++) acc[j] = 0.f;
    const float* hr = Hin + (size_t)row * KD;
    for (int k = 0; k < KD; k++) {
        float h = hr[k];
        const float* wr = &Ws[k * C + cg * 32];
        #pragma unroll
        for (int j = 0; j < 32; j++) acc[j] = fmaf(h, wr[j], acc[j]);
    }
    const float di = g_dinv[row];
    #pragma unroll
    for (int j = 0; j < 32; j++) {
        const int c = cg * 32 + j;
        const float y = acc[j];
        g_Y[(size_t)row * C + c] = y;
        atomicMax(&smax[c], __float_as_uint(fabsf(di * y)));
    }
    __syncthreads();
    for (int i = tid; i < C; i += nthreads) atomicMax(&g_colmax[i], smax[i]);
}

// ======================= kernel 2b: quantize B = dinv*Y to s8 limbs, [c][k] ==
// thread item: (c, 16-k chunk); lanes cover consecutive c -> coalesced Y reads
template <int C>
__global__ void __launch_bounds__(256) bquant_kernel() {
    const int id = blockIdx.x * 256 + threadIdx.x;
    const int c = id % C;
    const int k0 = (id / C) * 16;
    const float cm = __uint_as_float(g_colmax[c]);
    const float qs = (cm > 0.f) ? (QB / cm) : 0.f;
    char hb[16], lb[16];
    #pragma unroll
    for (int j = 0; j < 16; j++) {
        const int k = k0 + j;
        const float b = g_dinv[k] * g_Y[(size_t)k * C + c];
        int q = __float2int_rn(b * qs);
        int h = (q + 128) >> 8;
        hb[j] = (char)h;
        lb[j] = (char)(q - (h << 8));
    }
    *reinterpret_cast<int4*>(g_Bh + (size_t)c * N_NODES + k0) =
        *reinterpret_cast<const int4*>(hb);
    *reinterpret_cast<int4*>(g_Bl + (size_t)c * N_NODES + k0) =
        *reinterpret_cast<const int4*>(lb);
}

// ======================= kernel 3: s8 mma.sync GEMM  P = adj16 @ B16 =========
// CTA: 128 x C tile, K-chunk = 128 bytes, double-buffered cp.async, split-K=2.
// 8 warps 4(M) x 2(N); warp tile 32 x C/2.
// hh += Ah*Bh ; hx += Ah*Bl + Al*Bh ;  P = 65536*hh + 256*hx   (ll dropped)
// Smem rows 128B, chunk-XOR swizzle: off(row,kb) = row*128 + (kb ^ ((row&7)*16))
template <int C>
__global__ void __launch_bounds__(256, 1) gemm_kernel() {
    constexpr int BKB = 128;                  // K bytes (= elements) per chunk
    constexpr int AT = 128 * BKB;             // 16 KB per A limb tile
    constexpr int BT = C * BKB;
    constexpr int STAGE = 2 * AT + 2 * BT;    // Ah | Al | Bh | Bl
    constexpr int NKC = (N_NODES / 2) / BKB;  // 32 chunks (split-K=2)
    constexpr int NB = C / 16;
    constexpr int NG = C / 32;

    extern __shared__ __align__(128) uint8_t smem[];
    const uint32_t sb = smem_u32(smem);
    const int tid = threadIdx.x;
    const int wid = tid >> 5;
    const int lane = tid & 31;
    const int warpM = wid & 3;
    const int warpN = wid >> 2;
    const int m0 = blockIdx.x * 128;
    const int k0 = blockIdx.y * (N_NODES / 2);

    int hh[2][NB][4], hx[2][NB][4];
    #pragma unroll
    for (int mf = 0; mf < 2; mf++)
        #pragma unroll
        for (int nb = 0; nb < NB; nb++)
            #pragma unroll
            for (int j = 0; j < 4; j++) { hh[mf][nb][j] = 0; hx[mf][nb][j] = 0; }

    const int mat = lane >> 3;
    const int r = lane & 7;
    const int rx = r * 16;
    const int mrow0 = warpM * 32;
    const int nrow0 = warpN * (C / 2);

    // prologue: chunk 0
    {
        load_tile_async(g_Ah, m0, k0, sb, 128, tid);
        load_tile_async(g_Al, m0, k0, sb + AT, 128, tid);
        load_tile_async(g_Bh, 0, k0, sb + 2 * AT, C, tid);
        load_tile_async(g_Bl, 0, k0, sb + 2 * AT + BT, C, tid);
        cp_commit();
    }

    for (int kc = 0; kc < NKC; kc++) {
        if (kc + 1 < NKC) {
            const int kk = k0 + (kc + 1) * BKB;
            const uint32_t st = sb + ((kc + 1) & 1) * STAGE;
            load_tile_async(g_Ah, m0, kk, st, 128, tid);
            load_tile_async(g_Al, m0, kk, st + AT, 128, tid);
            load_tile_async(g_Bh, 0, kk, st + 2 * AT, C, tid);
            load_tile_async(g_Bl, 0, kk, st + 2 * AT + BT, C, tid);
            cp_commit();
            cp_wait<1>();   // chunk kc landed; kc+1 in flight
        } else {
            cp_wait<0>();
        }
        __syncthreads();

        const uint32_t st = sb + (kc & 1) * STAGE;
        const uint32_t sAh = st, sAl = st + AT;
        const uint32_t sBh = st + 2 * AT, sBl = st + 2 * AT + BT;

        #pragma unroll
        for (int ks = 0; ks < 4; ks++) {       // 32 k-bytes per step
            uint32_t ah[2][4], al[2][4];
            #pragma unroll
            for (int mf = 0; mf < 2; mf++) {
                const int rowA = mrow0 + mf * 16 + r + (mat & 1) * 8;
                const int kbA = ks * 32 + (mat >> 1) * 16;
                const uint32_t off = rowA * 128 + (kbA ^ rx);
                ldmx4(ah[mf], sAh + off);
                ldmx4(al[mf], sAl + off);
            }
            uint32_t bh[NG][4], bl[NG][4];
            #pragma unroll
            for (int g = 0; g < NG; g++) {
                const int rowB = nrow0 + g * 16 + r + (mat >> 1) * 8;
                const int kbB = ks * 32 + (mat & 1) * 16;
                const uint32_t off = rowB * 128 + (kbB ^ rx);
                ldmx4(bh[g], sBh + off);
                ldmx4(bl[g], sBl + off);
            }
            #pragma unroll
            for (int mf = 0; mf < 2; mf++) {
                #pragma unroll
                for (int g = 0; g < NG; g++) {
                    mma_s8(hh[mf][2 * g],     ah[mf], &bh[g][0]);
                    mma_s8(hh[mf][2 * g + 1], ah[mf], &bh[g][2]);
                    mma_s8(hx[mf][2 * g],     ah[mf], &bl[g][0]);
                    mma_s8(hx[mf][2 * g + 1], ah[mf], &bl[g][2]);
                    mma_s8(hx[mf][2 * g],     al[mf], &bh[g][0]);
                    mma_s8(hx[mf][2 * g + 1], al[mf], &bh[g][2]);
                }
            }
        }
        __syncthreads();
    }

    // ---- epilogue: combine limbs in fp32, write split-K partials ----
    const int g4 = lane >> 2, t4 = lane & 3;
    float* Pbase = g_P + (size_t)blockIdx.y * N_NODES * C;
    #pragma unroll
    for (int mf = 0; mf < 2; mf++) {
        #pragma unroll
        for (int nb = 0; nb < NB; nb++) {
            float v0 = 65536.f * (float)hh[mf][nb][0] + 256.f * (float)hx[mf][nb][0];
            float v1 = 65536.f * (float)hh[mf][nb][1] + 256.f * (float)hx[mf][nb][1];
            float v2 = 65536.f * (float)hh[mf][nb][2] + 256.f * (float)hx[mf][nb][2];
            float v3 = 65536.f * (float)hh[mf][nb][3] + 256.f * (float)hx[mf][nb][3];
            const int row = m0 + mrow0 + mf * 16 + g4;
            const int col = nrow0 + nb * 8 + t4 * 2;
            float* p = Pbase + (size_t)row * C + col;
            *reinterpret_cast<float2*>(p) = make_float2(v0, v1);
            *reinterpret_cast<float2*>(p + 8 * C) = make_float2(v2, v3);
        }
    }
}

// ======================= kernel 4: combine epilogue ==========================
// out = act( dinv_r * ( (P0+P1)*cscale_c + dinv_r * Y ) + bias_c )
// cscale_c = colmax_c / (QA*QB)
__global__ void __launch_bounds__(256) combine_kernel(const float* __restrict__ bias,
                                                      float* __restrict__ out,
                                                      int C, int relu) {
    const int i4 = blockIdx.x * blockDim.x + threadIdx.x;
    const int total = N_NODES * C / 4;
    if (i4 >= total) return;
    const size_t idx = (size_t)i4 * 4;
    const int row = (int)(idx / C);
    const int c = (int)(idx % C);
    const float di = g_dinv[row];
    const float iq = 1.f / (QA * QB);
    float cs0 = __uint_as_float(g_colmax[c + 0]) * iq;
    float cs1 = __uint_as_float(g_colmax[c + 1]) * iq;
    float cs2 = __uint_as_float(g_colmax[c + 2]) * iq;
    float cs3 = __uint_as_float(g_colmax[c + 3]) * iq;
    float4 p0 = *reinterpret_cast<const float4*>(&g_P[idx]);
    float4 p1 = *reinterpret_cast<const float4*>(&g_P[idx + (size_t)N_NODES * C]);
    float4 y  = *reinterpret_cast<const float4*>(&g_Y[idx]);
    float4 r;
    r.x = di * ((p0.x + p1.x) * cs0 + di * y.x) + bias[c + 0];
    r.y = di * ((p0.y + p1.y) * cs1 + di * y.y) + bias[c + 1];
    r.z = di * ((p0.z + p1.z) * cs2 + di * y.z) + bias[c + 2];
    r.w = di * ((p0.w + p1.w) * cs3 + di * y.w) + bias[c + 3];
    if (relu) {
        r.x = fmaxf(r.x, 0.f); r.y = fmaxf(r.y, 0.f);
        r.z = fmaxf(r.z, 0.f); r.w = fmaxf(r.w, 0.f);
    }
    *reinterpret_cast<float4*>(&out[idx]) = r;
}

// ======================= host side ===========================================
extern "C" void kernel_launch(void* const* d_in, const int* in_sizes, int n_in,
                              void* d_out, int out_size) {
    const float* x   = (const float*)d_in[0];
    const float* adj = (const float*)d_in[1];
    const float* W0  = (const float*)d_in[2];
    const float* b0  = (const float*)d_in[3];
    const float* W1  = (const float*)d_in[4];
    const float* b1  = (const float*)d_in[5];
    const float* W2  = (const float*)d_in[6];
    const float* b2  = (const float*)d_in[7];
    float* out = (float*)d_out;

    void* pH;
    cudaGetSymbolAddress(&pH, g_H);

    constexpr int SMEM128 = 2 * (2 * 128 * 128 + 2 * 128 * 128); // 131072
    constexpr int SMEM64  = 2 * (2 * 128 * 128 + 2 * 64 * 128);  //  98304
    cudaFuncSetAttribute(gemm_kernel<128>, cudaFuncAttributeMaxDynamicSharedMemorySize, SMEM128);
    cudaFuncSetAttribute(gemm_kernel<64>,  cudaFuncAttributeMaxDynamicSharedMemorySize, SMEM64);
    cudaFuncSetAttribute(y_kernel<128, 128>, cudaFuncAttributeMaxDynamicSharedMemorySize, 65536);

    const dim3 ggrid(N_NODES / 128, 2);   // 64 row tiles x split-K 2 = 128 CTAs

    // --- prep: rowsum -> dinv, adj -> s8 hi/lo limbs ---
    prep_kernel<<<N_NODES, 256>>>(adj);

    // --- layer 0 ---
    zero_cmax_kernel<<<1, 128>>>();
    y_kernel<64, 128><<<N_NODES / 64, 256, 64 * 128 * 4>>>(x, W0);
    bquant_kernel<128><<<(N_NODES / 16) * 128 / 256, 256>>>();
    gemm_kernel<128><<<ggrid, 256, SMEM128>>>();
    combine_kernel<<<(N_NODES * 128 / 4 + 255) / 256, 256>>>(b0, (float*)pH, 128, 1);

    // --- layer 1 ---
    zero_cmax_kernel<<<1, 128>>>();
    y_kernel<128, 128><<<N_NODES / 64, 256, 128 * 128 * 4>>>((const float*)pH, W1);
    bquant_kernel<128><<<(N_NODES / 16) * 128 / 256, 256>>>();
    gemm_kernel<128><<<ggrid, 256, SMEM128>>>();
    combine_kernel<<<(N_NODES * 128 / 4 + 255) / 256, 256>>>(b1, (float*)pH, 128, 1);

    // --- layer 2 (output, identity activation) ---
    zero_cmax_kernel<<<1, 128>>>();
    y_kernel<128, 64><<<N_NODES / 64, 128, 128 * 64 * 4>>>((const float*)pH, W2);
    bquant_kernel<64><<<(N_NODES / 16) * 64 / 256, 256>>>();
    gemm_kernel<64><<<ggrid, 256, SMEM64>>>();
    combine_kernel<<<(N_NODES * 64 / 4 + 255) / 256, 256>>>(b2, out, 64, 0);
}

// round 11
// speedup vs baseline: 2.2584x; 2.2584x over previous
#include <cuda_runtime.h>
#include <cuda_bf16.h>
#include <cstdint>
#include <cstddef>

#define N_NODES 8192
#define DHID 128

// ======================= device scratch (no cudaMalloc allowed) ==============
__device__ __align__(1024) __nv_bfloat16 g_Ahi[(size_t)N_NODES * N_NODES];   // 128 MB
__device__ __align__(1024) __nv_bfloat16 g_Alo[(size_t)N_NODES * N_NODES];   // 128 MB
__device__ __align__(1024) float         g_dinv[N_NODES];
__device__ __align__(1024) float         g_Y[(size_t)N_NODES * DHID];
__device__ __align__(1024) float         g_H[(size_t)N_NODES * DHID];
__device__ __align__(1024) float         g_P[2 * (size_t)N_NODES * DHID];    // split-K partials
__device__ __align__(1024) __nv_bfloat16 g_Bhi[(size_t)DHID * N_NODES];      // [c][k], K-major
__device__ __align__(1024) __nv_bfloat16 g_Blo[(size_t)DHID * N_NODES];

// ======================= helpers =============================================
__device__ __forceinline__ uint32_t smem_u32(const void* p) {
    uint32_t a;
    asm("{ .reg .u64 t; cvta.to.shared.u64 t, %1; cvt.u32.u64 %0, t; }" : "=r"(a) : "l"(p));
    return a;
}
__device__ __forceinline__ void cp_async16(uint32_t dst, const void* src) {
    asm volatile("cp.async.cg.shared.global [%0], [%1], 16;" :: "r"(dst), "l"(src) : "memory");
}
__device__ __forceinline__ void cp_commit() {
    asm volatile("cp.async.commit_group;" ::: "memory");
}
template <int N>
__device__ __forceinline__ void cp_wait() {
    asm volatile("cp.async.wait_group %0;" :: "n"(N) : "memory");
}
__device__ __forceinline__ void ldmx4(uint32_t* r, uint32_t addr) {
    asm volatile("ldmatrix.sync.aligned.m8n8.x4.shared.b16 {%0,%1,%2,%3}, [%4];"
                 : "=r"(r[0]), "=r"(r[1]), "=r"(r[2]), "=r"(r[3]) : "r"(addr));
}
__device__ __forceinline__ void mma16816(float* d, const uint32_t* a, const uint32_t* b) {
    asm volatile(
        "mma.sync.aligned.m16n8k16.row.col.f32.bf16.bf16.f32 "
        "{%0,%1,%2,%3}, {%4,%5,%6,%7}, {%8,%9}, {%0,%1,%2,%3};"
        : "+f"(d[0]), "+f"(d[1]), "+f"(d[2]), "+f"(d[3])
        : "r"(a[0]), "r"(a[1]), "r"(a[2]), "r"(a[3]), "r"(b[0]), "r"(b[1]));
}
__device__ __forceinline__ unsigned short bfu(__nv_bfloat16 h) {
    return *reinterpret_cast<unsigned short*>(&h);
}

// async tile loader: R rows x 64 bf16 (8 x 16B chunks per row), XOR swizzle
template <int NT>
__device__ __forceinline__ void load_tile_async(
    const __nv_bfloat16* __restrict__ src, int rowbase, int kk,
    uint32_t dst, int R, int tid) {
    for (int ch = tid; ch < R * 8; ch += NT) {
        const int row = ch >> 3;
        const int cb = ch & 7;
        const __nv_bfloat16* g = src + (size_t)(rowbase + row) * N_NODES + kk + cb * 8;
        const uint32_t s = dst + row * 128 + ((cb * 16) ^ ((row & 7) * 16));
        cp_async16(s, g);
    }
}

// ======================= kernel 1: rowsum + bf16 split of adjacency ==========
__global__ void __launch_bounds__(256) prep_kernel(const float* __restrict__ adj) {
    const int row = blockIdx.x;
    const int tid = threadIdx.x;
    const float4* src = reinterpret_cast<const float4*>(adj + (size_t)row * N_NODES);
    ushort4* dhi = reinterpret_cast<ushort4*>(g_Ahi + (size_t)row * N_NODES);
    ushort4* dlo = reinterpret_cast<ushort4*>(g_Alo + (size_t)row * N_NODES);
    float sum = 0.f;
    for (int i = tid; i < N_NODES / 4; i += 256) {
        float4 v = src[i];
        sum += (v.x + v.y) + (v.z + v.w);
        __nv_bfloat16 h0 = __float2bfloat16(v.x);
        __nv_bfloat16 h1 = __float2bfloat16(v.y);
        __nv_bfloat16 h2 = __float2bfloat16(v.z);
        __nv_bfloat16 h3 = __float2bfloat16(v.w);
        ushort4 hv; hv.x = bfu(h0); hv.y = bfu(h1); hv.z = bfu(h2); hv.w = bfu(h3);
        dhi[i] = hv;
        __nv_bfloat16 l0 = __float2bfloat16(v.x - __bfloat162float(h0));
        __nv_bfloat16 l1 = __float2bfloat16(v.y - __bfloat162float(h1));
        __nv_bfloat16 l2 = __float2bfloat16(v.z - __bfloat162float(h2));
        __nv_bfloat16 l3 = __float2bfloat16(v.w - __bfloat162float(h3));
        ushort4 lv; lv.x = bfu(l0); lv.y = bfu(l1); lv.z = bfu(l2); lv.w = bfu(l3);
        dlo[i] = lv;
    }
    #pragma unroll
    for (int o = 16; o; o >>= 1) sum += __shfl_xor_sync(0xffffffffu, sum, o);
    __shared__ float red[8];
    if ((tid & 31) == 0) red[tid >> 5] = sum;
    __syncthreads();
    if (tid == 0) {
        float s = 0.f;
        #pragma unroll
        for (int i = 0; i < 8; i++) s += red[i];
        g_dinv[row] = rsqrtf(s + 1.0f);   // A = adj + I
    }
}

// ======================= kernel 2: Y = H @ W  (+ scaled/split/transposed B) ===
template <int KD, int C>
__global__ void y_kernel(const float* __restrict__ Hin, const float* __restrict__ W) {
    extern __shared__ float Ws[];
    const int tid = threadIdx.x;
    const int nthreads = 64 * (C / 32);
    for (int i = tid; i < KD * C; i += nthreads) Ws[i] = W[i];
    __syncthreads();
    const int row = blockIdx.x * 64 + (tid & 63);
    const int cg = tid >> 6;
    float acc[32];
    #pragma unroll
    for (int j = 0; j < 32; j++) acc[j] = 0.f;
    const float* hr = Hin + (size_t)row * KD;
    for (int k = 0; k < KD; k++) {
        float h = hr[k];
        const float* wr = &Ws[k * C + cg * 32];
        #pragma unroll
        for (int j = 0; j < 32; j++) acc[j] = fmaf(h, wr[j], acc[j]);
    }
    const float di = g_dinv[row];
    #pragma unroll
    for (int j = 0; j < 32; j++) {
        const int c = cg * 32 + j;
        const float y = acc[j];
        g_Y[(size_t)row * C + c] = y;
        const float ys = di * y;
        __nv_bfloat16 h16 = __float2bfloat16(ys);
        float lo = ys - __bfloat162float(h16);
        g_Bhi[(size_t)c * N_NODES + row] = h16;
        g_Blo[(size_t)c * N_NODES + row] = __float2bfloat16(lo);
    }
}

// ======================= kernel 3: mma.sync GEMM  P = adj @ (dinv*Y) =========
// CTA: 128 x C output tile, BK=64, double-buffered cp.async, split-K=2.
// 16 warps in 4(M) x 4(N); warp tile 32 x C/4.
// acc += Ahi*Bhi + Ahi*Blo + Alo*Bhi  (bf16 split-2 emulation of fp32)
// Smem rows of 64 bf16 = 128B, chunk-XOR swizzle:
//   off(row, kbyte) = row*128 + (kbyte ^ ((row&7)*16))
template <int C>
__global__ void __launch_bounds__(512, 1) gemm_kernel() {
    constexpr int NT = 512;
    constexpr int BK = 64;
    constexpr int AT = 128 * 128;             // A operand tile bytes
    constexpr int BT = C * 128;               // B operand tile bytes
    constexpr int STAGE = 2 * AT + 2 * BT;    // Ahi | Alo | Bhi | Blo
    constexpr int NKC = (N_NODES / 2) / BK;   // 64 chunks per CTA (split-K=2)
    constexpr int WN = C / 4;                 // warp n-width
    constexpr int NB = WN / 8;                // n8-blocks per warp
    constexpr int NG = WN / 16;               // ldmatrix.x4 B groups per warp

    extern __shared__ __align__(128) uint8_t smem[];
    const uint32_t sb = smem_u32(smem);
    const int tid = threadIdx.x;
    const int wid = tid >> 5;
    const int lane = tid & 31;
    const int warpM = wid & 3;
    const int warpN = wid >> 2;               // 0..3
    const int m0 = blockIdx.x * 128;
    const int k0 = blockIdx.y * (N_NODES / 2);

    float acc[2][NB][4];
    #pragma unroll
    for (int mf = 0; mf < 2; mf++)
        #pragma unroll
        for (int nb = 0; nb < NB; nb++)
            #pragma unroll
            for (int j = 0; j < 4; j++) acc[mf][nb][j] = 0.f;

    // per-lane ldmatrix addressing components
    const int mat = lane >> 3;        // which 8x8 matrix this lane addresses
    const int r = lane & 7;           // row within the matrix
    const int rx = r * 16;            // swizzle XOR term (row origins are mult. of 8)
    const int mrow0 = warpM * 32;
    const int nrow0 = warpN * WN;

    // prologue: load chunk 0
    {
        load_tile_async<NT>(g_Ahi, m0, k0, sb, 128, tid);
        load_tile_async<NT>(g_Alo, m0, k0, sb + AT, 128, tid);
        load_tile_async<NT>(g_Bhi, 0, k0, sb + 2 * AT, C, tid);
        load_tile_async<NT>(g_Blo, 0, k0, sb + 2 * AT + BT, C, tid);
        cp_commit();
    }

    for (int kc = 0; kc < NKC; kc++) {
        // prefetch chunk kc+1 into the other buffer (safe: that buffer's last
        // compute ended with the __syncthreads() at the bottom of iter kc-1)
        if (kc + 1 < NKC) {
            const int kk = k0 + (kc + 1) * BK;
            const uint32_t st = sb + ((kc + 1) & 1) * STAGE;
            load_tile_async<NT>(g_Ahi, m0, kk, st, 128, tid);
            load_tile_async<NT>(g_Alo, m0, kk, st + AT, 128, tid);
            load_tile_async<NT>(g_Bhi, 0, kk, st + 2 * AT, C, tid);
            load_tile_async<NT>(g_Blo, 0, kk, st + 2 * AT + BT, C, tid);
            cp_commit();
            cp_wait<1>();   // chunk kc has landed; kc+1 still in flight
        } else {
            cp_wait<0>();
        }
        __syncthreads();

        const uint32_t st = sb + (kc & 1) * STAGE;
        const uint32_t sAhi = st, sAlo = st + AT;
        const uint32_t sBhi = st + 2 * AT, sBlo = st + 2 * AT + BT;

        #pragma unroll
        for (int ks = 0; ks < 4; ks++) {
            uint32_t ahi[2][4], alo[2][4];
            #pragma unroll
            for (int mf = 0; mf < 2; mf++) {
                const int rowA = mrow0 + mf * 16 + r + (mat & 1) * 8;
                const int kbA = ks * 32 + (mat >> 1) * 16;
                const uint32_t off = rowA * 128 + (kbA ^ rx);
                ldmx4(ahi[mf], sAhi + off);
                ldmx4(alo[mf], sAlo + off);
            }
            uint32_t bhi[NG][4], blo[NG][4];
            #pragma unroll
            for (int g = 0; g < NG; g++) {
                const int rowB = nrow0 + g * 16 + r + (mat >> 1) * 8;
                const int kbB = ks * 32 + (mat & 1) * 16;
                const uint32_t off = rowB * 128 + (kbB ^ rx);
                ldmx4(bhi[g], sBhi + off);
                ldmx4(blo[g], sBlo + off);
            }
            #pragma unroll
            for (int mf = 0; mf < 2; mf++) {
                #pragma unroll
                for (int g = 0; g < NG; g++) {
                    mma16816(acc[mf][2 * g],     ahi[mf], &bhi[g][0]);
                    mma16816(acc[mf][2 * g + 1], ahi[mf], &bhi[g][2]);
                    mma16816(acc[mf][2 * g],     ahi[mf], &blo[g][0]);
                    mma16816(acc[mf][2 * g + 1], ahi[mf], &blo[g][2]);
                    mma16816(acc[mf][2 * g],     alo[mf], &bhi[g][0]);
                    mma16816(acc[mf][2 * g + 1], alo[mf], &bhi[g][2]);
                }
            }
        }
        __syncthreads();
    }

    // ---- epilogue: write split-K partials ----
    const int g4 = lane >> 2, t4 = lane & 3;
    float* Pbase = g_P + (size_t)blockIdx.y * N_NODES * C;
    #pragma unroll
    for (int mf = 0; mf < 2; mf++) {
        #pragma unroll
        for (int nb = 0; nb < NB; nb++) {
            const int row = m0 + mrow0 + mf * 16 + g4;
            const int col = nrow0 + nb * 8 + t4 * 2;
            float* p = Pbase + (size_t)row * C + col;
            *reinterpret_cast<float2*>(p) =
                make_float2(acc[mf][nb][0], acc[mf][nb][1]);
            *reinterpret_cast<float2*>(p + 8 * C) =
                make_float2(acc[mf][nb][2], acc[mf][nb][3]);
        }
    }
}

// ======================= kernel 4: combine epilogue ==========================
// out_i = act( dinv_i * ( (P0+P1)_i + dinv_i * Y_i ) + b )    (+I folded in)
__global__ void __launch_bounds__(256) combine_kernel(const float* __restrict__ bias,
                                                      float* __restrict__ out,
                                                      int C, int relu) {
    const int i4 = blockIdx.x * blockDim.x + threadIdx.x;
    const int total = N_NODES * C / 4;
    if (i4 >= total) return;
    const size_t idx = (size_t)i4 * 4;
    const int row = (int)(idx / C);
    const int c = (int)(idx % C);
    const float di = g_dinv[row];
    float4 p0 = *reinterpret_cast<const float4*>(&g_P[idx]);
    float4 p1 = *reinterpret_cast<const float4*>(&g_P[idx + (size_t)N_NODES * C]);
    float4 y  = *reinterpret_cast<const float4*>(&g_Y[idx]);
    float4 r;
    r.x = di * ((p0.x + p1.x) + di * y.x) + bias[c + 0];
    r.y = di * ((p0.y + p1.y) + di * y.y) + bias[c + 1];
    r.z = di * ((p0.z + p1.z) + di * y.z) + bias[c + 2];
    r.w = di * ((p0.w + p1.w) + di * y.w) + bias[c + 3];
    if (relu) {
        r.x = fmaxf(r.x, 0.f); r.y = fmaxf(r.y, 0.f);
        r.z = fmaxf(r.z, 0.f); r.w = fmaxf(r.w, 0.f);
    }
    *reinterpret_cast<float4*>(&out[idx]) = r;
}

// ======================= host side ===========================================
extern "C" void kernel_launch(void* const* d_in, const int* in_sizes, int n_in,
                              void* d_out, int out_size) {
    const float* x   = (const float*)d_in[0];
    const float* adj = (const float*)d_in[1];
    const float* W0  = (const float*)d_in[2];
    const float* b0  = (const float*)d_in[3];
    const float* W1  = (const float*)d_in[4];
    const float* b1  = (const float*)d_in[5];
    const float* W2  = (const float*)d_in[6];
    const float* b2  = (const float*)d_in[7];
    float* out = (float*)d_out;

    void* pH;
    cudaGetSymbolAddress(&pH, g_H);

    constexpr int SMEM128 = 2 * (2 * 128 * 128 + 2 * 128 * 128); // 131072
    constexpr int SMEM64  = 2 * (2 * 128 * 128 + 2 * 64 * 128);  //  98304
    cudaFuncSetAttribute(gemm_kernel<128>, cudaFuncAttributeMaxDynamicSharedMemorySize, SMEM128);
    cudaFuncSetAttribute(gemm_kernel<64>,  cudaFuncAttributeMaxDynamicSharedMemorySize, SMEM64);
    cudaFuncSetAttribute(y_kernel<128, 128>, cudaFuncAttributeMaxDynamicSharedMemorySize, 65536);

    const dim3 ggrid(N_NODES / 128, 2);   // 64 row tiles x split-K 2 = 128 CTAs

    // --- prep: rowsum -> dinv, adj -> bf16 hi/lo ---
    prep_kernel<<<N_NODES, 256>>>(adj);

    // --- layer 0 ---
    y_kernel<64, 128><<<N_NODES / 64, 256, 64 * 128 * 4>>>(x, W0);
    gemm_kernel<128><<<ggrid, 512, SMEM128>>>();
    combine_kernel<<<(N_NODES * 128 / 4 + 255) / 256, 256>>>(b0, (float*)pH, 128, 1);

    // --- layer 1 ---
    y_kernel<128, 128><<<N_NODES / 64, 256, 128 * 128 * 4>>>((const float*)pH, W1);
    gemm_kernel<128><<<ggrid, 512, SMEM128>>>();
    combine_kernel<<<(N_NODES * 128 / 4 + 255) / 256, 256>>>(b1, (float*)pH, 128, 1);

    // --- layer 2 (output, identity activation) ---
    y_kernel<128, 64><<<N_NODES / 64, 128, 128 * 64 * 4>>>((const float*)pH, W2);
    gemm_kernel<64><<<ggrid, 512, SMEM64>>>();
    combine_kernel<<<(N_NODES * 64 / 4 + 255) / 256, 256>>>(b2, out, 64, 0);
}

// round 13
// speedup vs baseline: 2.8282x; 1.2523x over previous
#include <cuda_runtime.h>
#include <cuda_fp16.h>
#include <cstdint>
#include <cstddef>

#define N_NODES 8192
#define DHID 128

// ======================= device scratch (no cudaMalloc allowed) ==============
__device__ __align__(1024) __half g_Ahi[(size_t)N_NODES * N_NODES];   // 128 MB (fp16 hi limb)
__device__ __align__(1024) __half g_Alo[(size_t)N_NODES * N_NODES];   // 128 MB (fp16 lo limb)
__device__ __align__(1024) float  g_dinv[N_NODES];
__device__ __align__(1024) float  g_Y[(size_t)N_NODES * DHID];
__device__ __align__(1024) float  g_H[(size_t)N_NODES * DHID];
__device__ __align__(1024) float  g_P[2 * (size_t)N_NODES * DHID];    // split-K partials
__device__ __align__(1024) __half g_Bf[(size_t)DHID * N_NODES];       // [c][k] K-major, fp16

// ======================= helpers =============================================
__device__ __forceinline__ uint32_t smem_u32(const void* p) {
    uint32_t a;
    asm("{ .reg .u64 t; cvta.to.shared.u64 t, %1; cvt.u32.u64 %0, t; }" : "=r"(a) : "l"(p));
    return a;
}
__device__ __forceinline__ void cp_async16(uint32_t dst, const void* src) {
    asm volatile("cp.async.cg.shared.global [%0], [%1], 16;" :: "r"(dst), "l"(src) : "memory");
}
__device__ __forceinline__ void cp_commit() {
    asm volatile("cp.async.commit_group;" ::: "memory");
}
template <int N>
__device__ __forceinline__ void cp_wait() {
    asm volatile("cp.async.wait_group %0;" :: "n"(N) : "memory");
}
__device__ __forceinline__ void ldmx4(uint32_t* r, uint32_t addr) {
    asm volatile("ldmatrix.sync.aligned.m8n8.x4.shared.b16 {%0,%1,%2,%3}, [%4];"
                 : "=r"(r[0]), "=r"(r[1]), "=r"(r[2]), "=r"(r[3]) : "r"(addr));
}
__device__ __forceinline__ void mma16816(float* d, const uint32_t* a, const uint32_t* b) {
    asm volatile(
        "mma.sync.aligned.m16n8k16.row.col.f32.f16.f16.f32 "
        "{%0,%1,%2,%3}, {%4,%5,%6,%7}, {%8,%9}, {%0,%1,%2,%3};"
        : "+f"(d[0]), "+f"(d[1]), "+f"(d[2]), "+f"(d[3])
        : "r"(a[0]), "r"(a[1]), "r"(a[2]), "r"(a[3]), "r"(b[0]), "r"(b[1]));
}
__device__ __forceinline__ unsigned short hfu(__half h) {
    return *reinterpret_cast<unsigned short*>(&h);
}

// async tile loader: R rows x 64 fp16 (8 x 16B chunks per row), XOR swizzle
__device__ __forceinline__ void load_tile_async(
    const __half* __restrict__ src, int rowbase, int kk,
    uint32_t dst, int R, int tid) {
    for (int ch = tid; ch < R * 8; ch += 256) {
        const int row = ch >> 3;
        const int cb = ch & 7;
        const __half* g = src + (size_t)(rowbase + row) * N_NODES + kk + cb * 8;
        const uint32_t s = dst + row * 128 + ((cb * 16) ^ ((row & 7) * 16));
        cp_async16(s, g);
    }
}

// ======================= kernel 1: rowsum + fp16 split of adjacency ==========
__global__ void __launch_bounds__(256) prep_kernel(const float* __restrict__ adj) {
    const int row = blockIdx.x;
    const int tid = threadIdx.x;
    const float4* src = reinterpret_cast<const float4*>(adj + (size_t)row * N_NODES);
    ushort4* dhi = reinterpret_cast<ushort4*>(g_Ahi + (size_t)row * N_NODES);
    ushort4* dlo = reinterpret_cast<ushort4*>(g_Alo + (size_t)row * N_NODES);
    float sum = 0.f;
    for (int i = tid; i < N_NODES / 4; i += 256) {
        float4 v = src[i];
        sum += (v.x + v.y) + (v.z + v.w);
        __half h0 = __float2half_rn(v.x);
        __half h1 = __float2half_rn(v.y);
        __half h2 = __float2half_rn(v.z);
        __half h3 = __float2half_rn(v.w);
        ushort4 hv; hv.x = hfu(h0); hv.y = hfu(h1); hv.z = hfu(h2); hv.w = hfu(h3);
        dhi[i] = hv;
        __half l0 = __float2half_rn(v.x - __half2float(h0));
        __half l1 = __float2half_rn(v.y - __half2float(h1));
        __half l2 = __float2half_rn(v.z - __half2float(h2));
        __half l3 = __float2half_rn(v.w - __half2float(h3));
        ushort4 lv; lv.x = hfu(l0); lv.y = hfu(l1); lv.z = hfu(l2); lv.w = hfu(l3);
        dlo[i] = lv;
    }
    #pragma unroll
    for (int o = 16; o; o >>= 1) sum += __shfl_xor_sync(0xffffffffu, sum, o);
    __shared__ float red[8];
    if ((tid & 31) == 0) red[tid >> 5] = sum;
    __syncthreads();
    if (tid == 0) {
        float s = 0.f;
        #pragma unroll
        for (int i = 0; i < 8; i++) s += red[i];
        g_dinv[row] = rsqrtf(s + 1.0f);   // A = adj + I
    }
}

// ======================= kernel 2: Y = H @ W  (+ scaled fp16 B, transposed) ==
template <int KD, int C>
__global__ void y_kernel(const float* __restrict__ Hin, const float* __restrict__ W) {
    extern __shared__ float Ws[];
    const int tid = threadIdx.x;
    const int nthreads = 64 * (C / 32);
    for (int i = tid; i < KD * C; i += nthreads) Ws[i] = W[i];
    __syncthreads();
    const int row = blockIdx.x * 64 + (tid & 63);
    const int cg = tid >> 6;
    float acc[32];
    #pragma unroll
    for (int j = 0; j < 32; j++) acc[j] = 0.f;
    const float* hr = Hin + (size_t)row * KD;
    for (int k = 0; k < KD; k++) {
        float h = hr[k];
        const float* wr = &Ws[k * C + cg * 32];
        #pragma unroll
        for (int j = 0; j < 32; j++) acc[j] = fmaf(h, wr[j], acc[j]);
    }
    const float di = g_dinv[row];
    #pragma unroll
    for (int j = 0; j < 32; j++) {
        const int c = cg * 32 + j;
        const float y = acc[j];
        g_Y[(size_t)row * C + c] = y;
        g_Bf[(size_t)c * N_NODES + row] = __float2half_rn(di * y);
    }
}

// ======================= kernel 3: mma.sync GEMM  P = adj @ (dinv*Y) =========
// CTA: 128 x C output tile, BK=64, double-buffered cp.async, split-K=2.
// 8 warps in 4(M) x 2(N); warp tile 32 x C/2.
// acc += Ahi*B + Alo*B   (fp16 split-2 on A; B single fp16)
// Smem rows of 64 fp16 = 128B, chunk-XOR swizzle:
//   off(row, kbyte) = row*128 + (kbyte ^ ((row&7)*16))
template <int C>
__global__ void __launch_bounds__(256, 1) gemm_kernel() {
    constexpr int BK = 64;
    constexpr int AT = 128 * 128;             // A operand tile bytes
    constexpr int BT = C * 128;               // B operand tile bytes
    constexpr int STAGE = 2 * AT + BT;        // Ahi | Alo | B
    constexpr int NKC = (N_NODES / 2) / BK;   // 64 chunks per CTA (split-K=2)
    constexpr int NB = C / 16;                // n8-blocks per warp
    constexpr int NG = C / 32;                // ldmatrix.x4 B groups per warp

    extern __shared__ __align__(128) uint8_t smem[];
    const uint32_t sb = smem_u32(smem);
    const int tid = threadIdx.x;
    const int wid = tid >> 5;
    const int lane = tid & 31;
    const int warpM = wid & 3;
    const int warpN = wid >> 2;
    const int m0 = blockIdx.x * 128;
    const int k0 = blockIdx.y * (N_NODES / 2);

    float acc[2][NB][4];
    #pragma unroll
    for (int mf = 0; mf < 2; mf++)
        #pragma unroll
        for (int nb = 0; nb < NB; nb++)
            #pragma unroll
            for (int j = 0; j < 4; j++) acc[mf][nb][j] = 0.f;

    // per-lane ldmatrix addressing components
    const int mat = lane >> 3;
    const int r = lane & 7;
    const int rx = r * 16;
    const int mrow0 = warpM * 32;
    const int nrow0 = warpN * (C / 2);

    // prologue: load chunk 0
    {
        load_tile_async(g_Ahi, m0, k0, sb, 128, tid);
        load_tile_async(g_Alo, m0, k0, sb + AT, 128, tid);
        load_tile_async(g_Bf, 0, k0, sb + 2 * AT, C, tid);
        cp_commit();
    }

    for (int kc = 0; kc < NKC; kc++) {
        // prefetch chunk kc+1 into the other buffer
        if (kc + 1 < NKC) {
            const int kk = k0 + (kc + 1) * BK;
            const uint32_t st = sb + ((kc + 1) & 1) * STAGE;
            load_tile_async(g_Ahi, m0, kk, st, 128, tid);
            load_tile_async(g_Alo, m0, kk, st + AT, 128, tid);
            load_tile_async(g_Bf, 0, kk, st + 2 * AT, C, tid);
            cp_commit();
            cp_wait<1>();   // chunk kc has landed; kc+1 still in flight
        } else {
            cp_wait<0>();
        }
        __syncthreads();

        const uint32_t st = sb + (kc & 1) * STAGE;
        const uint32_t sAhi = st, sAlo = st + AT;
        const uint32_t sB = st + 2 * AT;

        #pragma unroll
        for (int ks = 0; ks < 4; ks++) {
            uint32_t ahi[2][4], alo[2][4];
            #pragma unroll
            for (int mf = 0; mf < 2; mf++) {
                const int rowA = mrow0 + mf * 16 + r + (mat & 1) * 8;
                const int kbA = ks * 32 + (mat >> 1) * 16;
                const uint32_t off = rowA * 128 + (kbA ^ rx);
                ldmx4(ahi[mf], sAhi + off);
                ldmx4(alo[mf], sAlo + off);
            }
            uint32_t bf[NG][4];
            #pragma unroll
            for (int g = 0; g < NG; g++) {
                const int rowB = nrow0 + g * 16 + r + (mat >> 1) * 8;
                const int kbB = ks * 32 + (mat & 1) * 16;
                const uint32_t off = rowB * 128 + (kbB ^ rx);
                ldmx4(bf[g], sB + off);
            }
            #pragma unroll
            for (int mf = 0; mf < 2; mf++) {
                #pragma unroll
                for (int g = 0; g < NG; g++) {
                    mma16816(acc[mf][2 * g],     ahi[mf], &bf[g][0]);
                    mma16816(acc[mf][2 * g + 1], ahi[mf], &bf[g][2]);
                    mma16816(acc[mf][2 * g],     alo[mf], &bf[g][0]);
                    mma16816(acc[mf][2 * g + 1], alo[mf], &bf[g][2]);
                }
            }
        }
        __syncthreads();
    }

    // ---- epilogue: write split-K partials ----
    const int g4 = lane >> 2, t4 = lane & 3;
    float* Pbase = g_P + (size_t)blockIdx.y * N_NODES * C;
    #pragma unroll
    for (int mf = 0; mf < 2; mf++) {
        #pragma unroll
        for (int nb = 0; nb < NB; nb++) {
            const int row = m0 + mrow0 + mf * 16 + g4;
            const int col = nrow0 + nb * 8 + t4 * 2;
            float* p = Pbase + (size_t)row * C + col;
            *reinterpret_cast<float2*>(p) =
                make_float2(acc[mf][nb][0], acc[mf][nb][1]);
            *reinterpret_cast<float2*>(p + 8 * C) =
                make_float2(acc[mf][nb][2], acc[mf][nb][3]);
        }
    }
}

// ======================= kernel 4: combine epilogue ==========================
// out_i = act( dinv_i * ( (P0+P1)_i + dinv_i * Y_i ) + b )    (+I folded in)
__global__ void __launch_bounds__(256) combine_kernel(const float* __restrict__ bias,
                                                      float* __restrict__ out,
                                                      int C, int relu) {
    const int i4 = blockIdx.x * blockDim.x + threadIdx.x;
    const int total = N_NODES * C / 4;
    if (i4 >= total) return;
    const size_t idx = (size_t)i4 * 4;
    const int row = (int)(idx / C);
    const int c = (int)(idx % C);
    const float di = g_dinv[row];
    float4 p0 = *reinterpret_cast<const float4*>(&g_P[idx]);
    float4 p1 = *reinterpret_cast<const float4*>(&g_P[idx + (size_t)N_NODES * C]);
    float4 y  = *reinterpret_cast<const float4*>(&g_Y[idx]);
    float4 r;
    r.x = di * ((p0.x + p1.x) + di * y.x) + bias[c + 0];
    r.y = di * ((p0.y + p1.y) + di * y.y) + bias[c + 1];
    r.z = di * ((p0.z + p1.z) + di * y.z) + bias[c + 2];
    r.w = di * ((p0.w + p1.w) + di * y.w) + bias[c + 3];
    if (relu) {
        r.x = fmaxf(r.x, 0.f); r.y = fmaxf(r.y, 0.f);
        r.z = fmaxf(r.z, 0.f); r.w = fmaxf(r.w, 0.f);
    }
    *reinterpret_cast<float4*>(&out[idx]) = r;
}

// ======================= host side ===========================================
extern "C" void kernel_launch(void* const* d_in, const int* in_sizes, int n_in,
                              void* d_out, int out_size) {
    const float* x   = (const float*)d_in[0];
    const float* adj = (const float*)d_in[1];
    const float* W0  = (const float*)d_in[2];
    const float* b0  = (const float*)d_in[3];
    const float* W1  = (const float*)d_in[4];
    const float* b1  = (const float*)d_in[5];
    const float* W2  = (const float*)d_in[6];
    const float* b2  = (const float*)d_in[7];
    float* out = (float*)d_out;

    void* pH;
    cudaGetSymbolAddress(&pH, g_H);

    constexpr int SMEM128 = 2 * (2 * 128 * 128 + 128 * 128); //  98304
    constexpr int SMEM64  = 2 * (2 * 128 * 128 + 64 * 128);  //  81920
    cudaFuncSetAttribute(gemm_kernel<128>, cudaFuncAttributeMaxDynamicSharedMemorySize, SMEM128);
    cudaFuncSetAttribute(gemm_kernel<64>,  cudaFuncAttributeMaxDynamicSharedMemorySize, SMEM64);
    cudaFuncSetAttribute(y_kernel<128, 128>, cudaFuncAttributeMaxDynamicSharedMemorySize, 65536);

    const dim3 ggrid(N_NODES / 128, 2);   // 64 row tiles x split-K 2 = 128 CTAs

    // --- prep: rowsum -> dinv, adj -> fp16 hi/lo ---
    prep_kernel<<<N_NODES, 256>>>(adj);

    // --- layer 0 ---
    y_kernel<64, 128><<<N_NODES / 64, 256, 64 * 128 * 4>>>(x, W0);
    gemm_kernel<128><<<ggrid, 256, SMEM128>>>();
    combine_kernel<<<(N_NODES * 128 / 4 + 255) / 256, 256>>>(b0, (float*)pH, 128, 1);

    // --- layer 1 ---
    y_kernel<128, 128><<<N_NODES / 64, 256, 128 * 128 * 4>>>((const float*)pH, W1);
    gemm_kernel<128><<<ggrid, 256, SMEM128>>>();
    combine_kernel<<<(N_NODES * 128 / 4 + 255) / 256, 256>>>(b1, (float*)pH, 128, 1);

    // --- layer 2 (output, identity activation) ---
    y_kernel<128, 64><<<N_NODES / 64, 128, 128 * 64 * 4>>>((const float*)pH, W2);
    gemm_kernel<64><<<ggrid, 256, SMEM64>>>();
    combine_kernel<<<(N_NODES * 64 / 4 + 255) / 256, 256>>>(b2, out, 64, 0);
}

// round 15
// speedup vs baseline: 3.8284x; 1.3536x over previous
#include <cuda_runtime.h>
#include <cuda_fp16.h>
#include <cstdint>
#include <cstddef>

#define N_NODES 8192
#define DHID 128

// ======================= device scratch (no cudaMalloc allowed) ==============
__device__ __align__(1024) __half g_Af[(size_t)N_NODES * N_NODES];    // 128 MB (fp16 adj)
__device__ __align__(1024) float  g_dinv[N_NODES];
__device__ __align__(1024) float  g_Y[(size_t)N_NODES * DHID];
__device__ __align__(1024) float  g_H[(size_t)N_NODES * DHID];
__device__ __align__(1024) float  g_P[2 * (size_t)N_NODES * DHID];    // split-K partials
__device__ __align__(1024) __half g_Bf[(size_t)DHID * N_NODES];       // [c][k] K-major, fp16

// ======================= helpers =============================================
__device__ __forceinline__ uint32_t smem_u32(const void* p) {
    uint32_t a;
    asm("{ .reg .u64 t; cvta.to.shared.u64 t, %1; cvt.u32.u64 %0, t; }" : "=r"(a) : "l"(p));
    return a;
}
__device__ __forceinline__ void cp_async16(uint32_t dst, const void* src) {
    asm volatile("cp.async.cg.shared.global [%0], [%1], 16;" :: "r"(dst), "l"(src) : "memory");
}
__device__ __forceinline__ void cp_commit() {
    asm volatile("cp.async.commit_group;" ::: "memory");
}
template <int N>
__device__ __forceinline__ void cp_wait() {
    asm volatile("cp.async.wait_group %0;" :: "n"(N) : "memory");
}
__device__ __forceinline__ void ldmx4(uint32_t* r, uint32_t addr) {
    asm volatile("ldmatrix.sync.aligned.m8n8.x4.shared.b16 {%0,%1,%2,%3}, [%4];"
                 : "=r"(r[0]), "=r"(r[1]), "=r"(r[2]), "=r"(r[3]) : "r"(addr));
}
__device__ __forceinline__ void mma16816(float* d, const uint32_t* a, const uint32_t* b) {
    asm volatile(
        "mma.sync.aligned.m16n8k16.row.col.f32.f16.f16.f32 "
        "{%0,%1,%2,%3}, {%4,%5,%6,%7}, {%8,%9}, {%0,%1,%2,%3};"
        : "+f"(d[0]), "+f"(d[1]), "+f"(d[2]), "+f"(d[3])
        : "r"(a[0]), "r"(a[1]), "r"(a[2]), "r"(a[3]), "r"(b[0]), "r"(b[1]));
}
__device__ __forceinline__ unsigned short hfu(__half h) {
    return *reinterpret_cast<unsigned short*>(&h);
}

// async tile loader: R rows x 64 fp16 (8 x 16B chunks per row), XOR swizzle
__device__ __forceinline__ void load_tile_async(
    const __half* __restrict__ src, int rowbase, int kk,
    uint32_t dst, int R, int tid) {
    for (int ch = tid; ch < R * 8; ch += 256) {
        const int row = ch >> 3;
        const int cb = ch & 7;
        const __half* g = src + (size_t)(rowbase + row) * N_NODES + kk + cb * 8;
        const uint32_t s = dst + row * 128 + ((cb * 16) ^ ((row & 7) * 16));
        cp_async16(s, g);
    }
}

// ======================= kernel 1: rowsum + fp16 cast of adjacency ===========
__global__ void __launch_bounds__(256) prep_kernel(const float* __restrict__ adj) {
    const int row = blockIdx.x;
    const int tid = threadIdx.x;
    const float4* src = reinterpret_cast<const float4*>(adj + (size_t)row * N_NODES);
    ushort4* dst = reinterpret_cast<ushort4*>(g_Af + (size_t)row * N_NODES);
    float sum = 0.f;
    for (int i = tid; i < N_NODES / 4; i += 256) {
        float4 v = src[i];
        sum += (v.x + v.y) + (v.z + v.w);
        ushort4 hv;
        hv.x = hfu(__float2half_rn(v.x));
        hv.y = hfu(__float2half_rn(v.y));
        hv.z = hfu(__float2half_rn(v.z));
        hv.w = hfu(__float2half_rn(v.w));
        dst[i] = hv;
    }
    #pragma unroll
    for (int o = 16; o; o >>= 1) sum += __shfl_xor_sync(0xffffffffu, sum, o);
    __shared__ float red[8];
    if ((tid & 31) == 0) red[tid >> 5] = sum;
    __syncthreads();
    if (tid == 0) {
        float s = 0.f;
        #pragma unroll
        for (int i = 0; i < 8; i++) s += red[i];
        g_dinv[row] = rsqrtf(s + 1.0f);   // A = adj + I
    }
}

// ======================= kernel 2: Y = H @ W  (+ scaled fp16 B, transposed) ==
template <int KD, int C>
__global__ void y_kernel(const float* __restrict__ Hin, const float* __restrict__ W) {
    extern __shared__ float Ws[];
    const int tid = threadIdx.x;
    const int nthreads = 64 * (C / 32);
    for (int i = tid; i < KD * C; i += nthreads) Ws[i] = W[i];
    __syncthreads();
    const int row = blockIdx.x * 64 + (tid & 63);
    const int cg = tid >> 6;
    float acc[32];
    #pragma unroll
    for (int j = 0; j < 32; j++) acc[j] = 0.f;
    const float* hr = Hin + (size_t)row * KD;
    for (int k = 0; k < KD; k++) {
        float h = hr[k];
        const float* wr = &Ws[k * C + cg * 32];
        #pragma unroll
        for (int j = 0; j < 32; j++) acc[j] = fmaf(h, wr[j], acc[j]);
    }
    const float di = g_dinv[row];
    #pragma unroll
    for (int j = 0; j < 32; j++) {
        const int c = cg * 32 + j;
        const float y = acc[j];
        g_Y[(size_t)row * C + c] = y;
        g_Bf[(size_t)c * N_NODES + row] = __float2half_rn(di * y);
    }
}

// ======================= kernel 3: mma.sync GEMM  P = adj @ (dinv*Y) =========
// CTA: 128 x C output tile, BK=64, double-buffered cp.async, split-K=2.
// 8 warps in 4(M) x 2(N); warp tile 32 x C/2.  acc += A*B, single fp16 product.
// Smem rows of 64 fp16 = 128B, chunk-XOR swizzle:
//   off(row, kbyte) = row*128 + (kbyte ^ ((row&7)*16))
template <int C>
__global__ void __launch_bounds__(256, 1) gemm_kernel() {
    constexpr int BK = 64;
    constexpr int AT = 128 * 128;             // A tile bytes
    constexpr int BT = C * 128;               // B tile bytes
    constexpr int STAGE = AT + BT;            // A | B
    constexpr int NKC = (N_NODES / 2) / BK;   // 64 chunks per CTA (split-K=2)
    constexpr int NB = C / 16;                // n8-blocks per warp
    constexpr int NG = C / 32;                // ldmatrix.x4 B groups per warp

    extern __shared__ __align__(128) uint8_t smem[];
    const uint32_t sb = smem_u32(smem);
    const int tid = threadIdx.x;
    const int wid = tid >> 5;
    const int lane = tid & 31;
    const int warpM = wid & 3;
    const int warpN = wid >> 2;
    const int m0 = blockIdx.x * 128;
    const int k0 = blockIdx.y * (N_NODES / 2);

    float acc[2][NB][4];
    #pragma unroll
    for (int mf = 0; mf < 2; mf++)
        #pragma unroll
        for (int nb = 0; nb < NB; nb++)
            #pragma unroll
            for (int j = 0; j < 4; j++) acc[mf][nb][j] = 0.f;

    const int mat = lane >> 3;
    const int r = lane & 7;
    const int rx = r * 16;
    const int mrow0 = warpM * 32;
    const int nrow0 = warpN * (C / 2);

    // prologue: load chunk 0
    {
        load_tile_async(g_Af, m0, k0, sb, 128, tid);
        load_tile_async(g_Bf, 0, k0, sb + AT, C, tid);
        cp_commit();
    }

    for (int kc = 0; kc < NKC; kc++) {
        // prefetch chunk kc+1 into the other buffer
        if (kc + 1 < NKC) {
            const int kk = k0 + (kc + 1) * BK;
            const uint32_t st = sb + ((kc + 1) & 1) * STAGE;
            load_tile_async(g_Af, m0, kk, st, 128, tid);
            load_tile_async(g_Bf, 0, kk, st + AT, C, tid);
            cp_commit();
            cp_wait<1>();   // chunk kc has landed; kc+1 still in flight
        } else {
            cp_wait<0>();
        }
        __syncthreads();

        const uint32_t st = sb + (kc & 1) * STAGE;
        const uint32_t sA = st;
        const uint32_t sB = st + AT;

        #pragma unroll
        for (int ks = 0; ks < 4; ks++) {
            uint32_t af[2][4];
            #pragma unroll
            for (int mf = 0; mf < 2; mf++) {
                const int rowA = mrow0 + mf * 16 + r + (mat & 1) * 8;
                const int kbA = ks * 32 + (mat >> 1) * 16;
                const uint32_t off = rowA * 128 + (kbA ^ rx);
                ldmx4(af[mf], sA + off);
            }
            uint32_t bf[NG][4];
            #pragma unroll
            for (int g = 0; g < NG; g++) {
                const int rowB = nrow0 + g * 16 + r + (mat >> 1) * 8;
                const int kbB = ks * 32 + (mat & 1) * 16;
                const uint32_t off = rowB * 128 + (kbB ^ rx);
                ldmx4(bf[g], sB + off);
            }
            #pragma unroll
            for (int mf = 0; mf < 2; mf++) {
                #pragma unroll
                for (int g = 0; g < NG; g++) {
                    mma16816(acc[mf][2 * g],     af[mf], &bf[g][0]);
                    mma16816(acc[mf][2 * g + 1], af[mf], &bf[g][2]);
                }
            }
        }
        __syncthreads();
    }

    // ---- epilogue: write split-K partials ----
    const int g4 = lane >> 2, t4 = lane & 3;
    float* Pbase = g_P + (size_t)blockIdx.y * N_NODES * C;
    #pragma unroll
    for (int mf = 0; mf < 2; mf++) {
        #pragma unroll
        for (int nb = 0; nb < NB; nb++) {
            const int row = m0 + mrow0 + mf * 16 + g4;
            const int col = nrow0 + nb * 8 + t4 * 2;
            float* p = Pbase + (size_t)row * C + col;
            *reinterpret_cast<float2*>(p) =
                make_float2(acc[mf][nb][0], acc[mf][nb][1]);
            *reinterpret_cast<float2*>(p + 8 * C) =
                make_float2(acc[mf][nb][2], acc[mf][nb][3]);
        }
    }
}

// ======================= kernel 4: combine epilogue ==========================
// out_i = act( dinv_i * ( (P0+P1)_i + dinv_i * Y_i ) + b )    (+I folded in)
__global__ void __launch_bounds__(256) combine_kernel(const float* __restrict__ bias,
                                                      float* __restrict__ out,
                                                      int C, int relu) {
    const int i4 = blockIdx.x * blockDim.x + threadIdx.x;
    const int total = N_NODES * C / 4;
    if (i4 >= total) return;
    const size_t idx = (size_t)i4 * 4;
    const int row = (int)(idx / C);
    const int c = (int)(idx % C);
    const float di = g_dinv[row];
    float4 p0 = *reinterpret_cast<const float4*>(&g_P[idx]);
    float4 p1 = *reinterpret_cast<const float4*>(&g_P[idx + (size_t)N_NODES * C]);
    float4 y  = *reinterpret_cast<const float4*>(&g_Y[idx]);
    float4 r;
    r.x = di * ((p0.x + p1.x) + di * y.x) + bias[c + 0];
    r.y = di * ((p0.y + p1.y) + di * y.y) + bias[c + 1];
    r.z = di * ((p0.z + p1.z) + di * y.z) + bias[c + 2];
    r.w = di * ((p0.w + p1.w) + di * y.w) + bias[c + 3];
    if (relu) {
        r.x = fmaxf(r.x, 0.f); r.y = fmaxf(r.y, 0.f);
        r.z = fmaxf(r.z, 0.f); r.w = fmaxf(r.w, 0.f);
    }
    *reinterpret_cast<float4*>(&out[idx]) = r;
}

// ======================= host side ===========================================
extern "C" void kernel_launch(void* const* d_in, const int* in_sizes, int n_in,
                              void* d_out, int out_size) {
    const float* x   = (const float*)d_in[0];
    const float* adj = (const float*)d_in[1];
    const float* W0  = (const float*)d_in[2];
    const float* b0  = (const float*)d_in[3];
    const float* W1  = (const float*)d_in[4];
    const float* b1  = (const float*)d_in[5];
    const float* W2  = (const float*)d_in[6];
    const float* b2  = (const float*)d_in[7];
    float* out = (float*)d_out;

    void* pH;
    cudaGetSymbolAddress(&pH, g_H);

    constexpr int SMEM128 = 2 * (128 * 128 + 128 * 128); // 65536
    constexpr int SMEM64  = 2 * (128 * 128 + 64 * 128);  // 49152
    cudaFuncSetAttribute(gemm_kernel<128>, cudaFuncAttributeMaxDynamicSharedMemorySize, SMEM128);
    cudaFuncSetAttribute(gemm_kernel<64>,  cudaFuncAttributeMaxDynamicSharedMemorySize, SMEM64);
    cudaFuncSetAttribute(y_kernel<128, 128>, cudaFuncAttributeMaxDynamicSharedMemorySize, 65536);

    const dim3 ggrid(N_NODES / 128, 2);   // 64 row tiles x split-K 2 = 128 CTAs

    // --- prep: rowsum -> dinv, adj -> fp16 ---
    prep_kernel<<<N_NODES, 256>>>(adj);

    // --- layer 0 ---
    y_kernel<64, 128><<<N_NODES / 64, 256, 64 * 128 * 4>>>(x, W0);
    gemm_kernel<128><<<ggrid, 256, SMEM128>>>();
    combine_kernel<<<(N_NODES * 128 / 4 + 255) / 256, 256>>>(b0, (float*)pH, 128, 1);

    // --- layer 1 ---
    y_kernel<128, 128><<<N_NODES / 64, 256, 128 * 128 * 4>>>((const float*)pH, W1);
    gemm_kernel<128><<<ggrid, 256, SMEM128>>>();
    combine_kernel<<<(N_NODES * 128 / 4 + 255) / 256, 256>>>(b1, (float*)pH, 128, 1);

    // --- layer 2 (output, identity activation) ---
    y_kernel<128, 64><<<N_NODES / 64, 128, 128 * 64 * 4>>>((const float*)pH, W2);
    gemm_kernel<64><<<ggrid, 256, SMEM64>>>();
    combine_kernel<<<(N_NODES * 64 / 4 + 255) / 256, 256>>>(b2, out, 64, 0);
}